// round 14
// baseline (speedup 1.0000x reference)
#include <cuda_runtime.h>
#include <cuda_fp16.h>
#include <cstdint>

// ---------------------------------------------------------------------------
// TemporalAttention on sm_103a (compute_103-safe: mma.sync + ldmatrix + cp.async).
// GEMMs: fp16 x fp16 -> fp32 mma.sync.m16n8k16, CTA tile 128x128, warp 64x32,
//        cp.async 3-stage ring (single barrier per stage), 2 CTAs/SM.
// Attention: per-warp tensor-core flash (S-mma -> reg softmax -> PV-mma).
// B=8192, F=16, C=512, H=8, Dh=64.  M = B*F = 131072.
// ---------------------------------------------------------------------------

#define CDIM  512
#define NHEAD 8
#define DHEAD 64
#define NFRM  16

__device__ __half g_qh[67108864];
__device__ __half g_kh[67108864];
__device__ __half g_vh[67108864];
__device__ __half g_h16[67108864];    // cvt(X) each launch; attn overwrites with its output
__device__ __half g_w16[4][262144];   // transposed fp16 weights: w[n][k] = W[k][n]

// ------------------------------ helpers ------------------------------------
__device__ __forceinline__ uint32_t smem_u32(const void* p) {
    uint32_t a;
    asm("{ .reg .u64 t; cvta.to.shared.u64 t, %1; cvt.u32.u64 %0, t; }" : "=r"(a) : "l"(p));
    return a;
}

__device__ __forceinline__ void ldsm_x4(uint32_t r[4], uint32_t addr) {
    asm volatile("ldmatrix.sync.aligned.m8n8.x4.shared.b16 {%0,%1,%2,%3}, [%4];"
                 : "=r"(r[0]), "=r"(r[1]), "=r"(r[2]), "=r"(r[3]) : "r"(addr));
}
__device__ __forceinline__ void ldsm_x4_t(uint32_t r[4], uint32_t addr) {
    asm volatile("ldmatrix.sync.aligned.m8n8.x4.trans.shared.b16 {%0,%1,%2,%3}, [%4];"
                 : "=r"(r[0]), "=r"(r[1]), "=r"(r[2]), "=r"(r[3]) : "r"(addr));
}

__device__ __forceinline__ void mma_f16(float c[4], const uint32_t a[4],
                                        uint32_t b0, uint32_t b1) {
    asm volatile(
        "mma.sync.aligned.m16n8k16.row.col.f32.f16.f16.f32 "
        "{%0,%1,%2,%3},{%4,%5,%6,%7},{%8,%9},{%0,%1,%2,%3};"
        : "+f"(c[0]), "+f"(c[1]), "+f"(c[2]), "+f"(c[3])
        : "r"(a[0]), "r"(a[1]), "r"(a[2]), "r"(a[3]), "r"(b0), "r"(b1));
}

__device__ __forceinline__ void cp16(uint32_t dst, const void* src) {
    asm volatile("cp.async.cg.shared.global [%0], [%1], 16;" :: "r"(dst), "l"(src));
}

// ---------------------------------------------------------------------------
// 128x128x512 tile GEMM: C = A16[rowBase:+128,:] @ Bw16[colBase:+128,:]^T
// A16 [M,512] fp16 row-major; Bw16 [512,512] fp16 stored [n][k] row-major.
// 256 threads = 8 warps (2m x 4n), warp tile 64x32, smem rows 40 halves (80B),
// K staged 32-wide, cp.async 3-stage ring, one __syncthreads per stage.
// Output: fp16 (Ch) when Ch != nullptr, else fp32 (+bias) to Cf.
// ---------------------------------------------------------------------------
__device__ __forceinline__ void stage_in(uint32_t aB, uint32_t bB,
                                         const __half* Ag, const __half* Bg, int kt,
                                         int tid)
{
    const int row0 = tid >> 2;
    const int kg   = tid & 3;
#pragma unroll
    for (int i = 0; i < 2; i++) {
        int row = row0 + i * 64;
        uint32_t off = (uint32_t)(row * 80 + kg * 16);
        cp16(aB + off, Ag + (size_t)row * CDIM + kt + kg * 8);
        cp16(bB + off, Bg + (size_t)row * CDIM + kt + kg * 8);
    }
    asm volatile("cp.async.commit_group;" ::: "memory");
}

__device__ __forceinline__ void gemm_tc(const __half* __restrict__ A16,
                                        const __half* __restrict__ Bw16,
                                        float* __restrict__ Cf, __half* __restrict__ Ch,
                                        const float* __restrict__ bias,
                                        int rowBase, int colBase)
{
    __shared__ alignas(128) __half sA[3][128 * 40];
    __shared__ alignas(128) __half sB[3][128 * 40];

    const int tid  = threadIdx.x;
    const int lane = tid & 31;
    const int warp = tid >> 5;
    const int m0 = (warp >> 2) * 64;
    const int n0 = (warp & 3) * 32;
    const int tg = lane & 3;
    const int gp = lane >> 2;

    float acc[4][4][4];
#pragma unroll
    for (int mt = 0; mt < 4; mt++)
#pragma unroll
        for (int nt = 0; nt < 4; nt++)
#pragma unroll
            for (int r = 0; r < 4; r++) acc[mt][nt][r] = 0.0f;

    const uint32_t aAddr[3] = { smem_u32(sA[0]), smem_u32(sA[1]), smem_u32(sA[2]) };
    const uint32_t bAddr[3] = { smem_u32(sB[0]), smem_u32(sB[1]), smem_u32(sB[2]) };

    const uint32_t aOff = (uint32_t)((lane & 15) * 80 + ((lane >> 4) & 1) * 16);
    const uint32_t bOff = (uint32_t)(((lane & 7) + ((lane >> 4) & 1) * 8) * 80
                                     + ((lane >> 3) & 1) * 16);

    const __half* Ag = A16 + (size_t)rowBase * CDIM;
    const __half* Bg = Bw16 + (size_t)colBase * CDIM;

    // prologue: stages 0 and 1 in flight
    stage_in(aAddr[0], bAddr[0], Ag, Bg, 0, tid);
    stage_in(aAddr[1], bAddr[1], Ag, Bg, 32, tid);

    int buf = 0;
    for (int s = 0; s < 16; s++) {
        if (s < 15) asm volatile("cp.async.wait_group 1;" ::: "memory");
        else        asm volatile("cp.async.wait_group 0;" ::: "memory");
        __syncthreads();   // all warps done with buf (s-1)%3 -> safe to refill as s+2

        if (s + 2 < 16) {
            int nb = (buf + 2 >= 3) ? buf - 1 : buf + 2;
            stage_in(aAddr[nb], bAddr[nb], Ag, Bg, (s + 2) * 32, tid);
        }

        const uint32_t aP = aAddr[buf] + aOff;
        const uint32_t bP = bAddr[buf] + bOff;
#pragma unroll
        for (int k16 = 0; k16 < 2; k16++) {
            uint32_t af[4][4];
            uint32_t bf[2][4];
#pragma unroll
            for (int mt = 0; mt < 4; mt++)
                ldsm_x4(af[mt], aP + (uint32_t)((m0 + mt * 16) * 80 + k16 * 32));
#pragma unroll
            for (int nt2 = 0; nt2 < 2; nt2++)
                ldsm_x4(bf[nt2], bP + (uint32_t)((n0 + nt2 * 16) * 80 + k16 * 32));
#pragma unroll
            for (int mt = 0; mt < 4; mt++)
#pragma unroll
                for (int nt = 0; nt < 4; nt++)
                    mma_f16(acc[mt][nt], af[mt],
                            bf[nt >> 1][(nt & 1) * 2], bf[nt >> 1][(nt & 1) * 2 + 1]);
        }
        buf = (buf + 1 >= 3) ? 0 : buf + 1;
    }

#pragma unroll
    for (int mt = 0; mt < 4; mt++) {
#pragma unroll
        for (int nt = 0; nt < 4; nt++) {
            int r   = rowBase + m0 + mt * 16 + gp;
            int cix = colBase + n0 + nt * 8 + tg * 2;
            if (Ch) {
                __half2 h0 = __floats2half2_rn(acc[mt][nt][0], acc[mt][nt][1]);
                __half2 h1 = __floats2half2_rn(acc[mt][nt][2], acc[mt][nt][3]);
                *(__half2*)&Ch[(size_t)r * CDIM + cix]       = h0;
                *(__half2*)&Ch[(size_t)(r + 8) * CDIM + cix] = h1;
            } else {
                float2 t0 = make_float2(acc[mt][nt][0], acc[mt][nt][1]);
                float2 t1 = make_float2(acc[mt][nt][2], acc[mt][nt][3]);
                float b0v = bias[cix], b1v = bias[cix + 1];
                t0.x += b0v; t0.y += b1v;
                t1.x += b0v; t1.y += b1v;
                *(float2*)&Cf[(size_t)r * CDIM + cix]       = t0;
                *(float2*)&Cf[(size_t)(r + 8) * CDIM + cix] = t1;
            }
        }
    }
}

// grid (12, 1024): x>>2 selects q/k/v, x&3 selects 128-col slab
__global__ void __launch_bounds__(256, 2)
qkv_kernel()
{
    int sel = blockIdx.x >> 2;
    __half* Cd = (sel == 0) ? g_qh : (sel == 1) ? g_kh : g_vh;
    gemm_tc(g_h16, g_w16[sel], nullptr, Cd, nullptr, blockIdx.y * 128, (blockIdx.x & 3) * 128);
}

// grid (4, 1024)
__global__ void __launch_bounds__(256, 2)
out_kernel(const float* __restrict__ bo, float* __restrict__ out)
{
    gemm_tc(g_h16, g_w16[3], out, nullptr, bo, blockIdx.y * 128, blockIdx.x * 128);
}

// ---------------------------------------------------------------------------
// prep: X fp32 -> fp16 ; W[k][n] fp32 -> w16[n][k] fp16 (transposed)
// ---------------------------------------------------------------------------
__global__ void cvt_x_kernel(const float* __restrict__ X)
{
    size_t i = ((size_t)blockIdx.x * blockDim.x + threadIdx.x) * 4;
    float4 v = *(const float4*)(X + i);
    __half2 hh[2];
    hh[0] = __floats2half2_rn(v.x, v.y);
    hh[1] = __floats2half2_rn(v.z, v.w);
    *(uint2*)&g_h16[i] = *(uint2*)hh;
}

__global__ void prep_w_kernel(const float* __restrict__ Wq, const float* __restrict__ Wk,
                              const float* __restrict__ Wv, const float* __restrict__ Wo)
{
    __shared__ float t[32][33];
    const float* W = (blockIdx.z == 0) ? Wq : (blockIdx.z == 1) ? Wk
                   : (blockIdx.z == 2) ? Wv : Wo;
    int n0 = blockIdx.x * 32, k0 = blockIdx.y * 32;
    for (int rr = threadIdx.y; rr < 32; rr += 8)
        t[rr][threadIdx.x] = W[(size_t)(k0 + rr) * CDIM + n0 + threadIdx.x];
    __syncthreads();
    for (int rr = threadIdx.y; rr < 32; rr += 8)
        g_w16[blockIdx.z][(size_t)(n0 + rr) * CDIM + k0 + threadIdx.x] =
            __float2half_rn(t[threadIdx.x][rr]);
}

// ---------------------------------------------------------------------------
// Attention: one warp per (batch, head). Tensor-core S = Q K^T (m16n8k16),
// softmax in registers (S-acc layout == next mma's A-frag layout), then
// O = P V with V fragments via ldmatrix.trans. Output fp16 into g_h16.
// ---------------------------------------------------------------------------
__device__ __forceinline__ int t5_bucket(int rel) {  // rel = j - i
    int n = -rel;
    int ret = 0;
    if (n < 0) { ret = 16; n = -n; }
    if (n < 8) return ret + n;
    int v = 8 + (int)(logf((float)n * 0.125f) * (8.0f / logf(16.0f)));
    if (v > 15) v = 15;
    return ret + v;
}

__global__ void __launch_bounds__(128)
attn_kernel(const float* __restrict__ table)
{
    __shared__ alignas(16) __half sQ[4][NFRM][72];   // reused as output staging
    __shared__ alignas(16) __half sK[4][NFRM][72];
    __shared__ alignas(16) __half sV[4][NFRM][72];
    __shared__ float stab[32 * NHEAD];
    __shared__ int   sbkt[31];

    const int tid  = threadIdx.x;
    const int lane = tid & 31;
    const int warp = tid >> 5;

    for (int t = tid; t < 32 * NHEAD; t += 128) stab[t] = table[t];
    if (tid < 31) sbkt[tid] = t5_bucket(tid - 15);
    __syncthreads();

    const int b = blockIdx.x >> 1;
    const int h = ((blockIdx.x & 1) << 2) + warp;
    const size_t base = (size_t)b * NFRM * CDIM + (size_t)h * DHEAD;

    for (int t = lane; t < 128; t += 32) {
        int f = t >> 3, c = (t & 7) * 8;
        size_t g = base + (size_t)f * CDIM + c;
        *(uint4*)&sQ[warp][f][c] = *(const uint4*)&g_qh[g];
        *(uint4*)&sK[warp][f][c] = *(const uint4*)&g_kh[g];
        *(uint4*)&sV[warp][f][c] = *(const uint4*)&g_vh[g];
    }
    __syncwarp();

    const uint32_t lrow = (uint32_t)((lane & 15) * 144 + ((lane >> 4) & 1) * 16);
    const uint32_t qPtr = smem_u32(&sQ[warp][0][0]) + lrow;
    const uint32_t kPtr = smem_u32(&sK[warp][0][0]) + lrow;
    const uint32_t vPtr = smem_u32(&sV[warp][0][0]) + lrow;

    const int gp = lane >> 2;
    const int tg = lane & 3;

    float sc[2][4];
#pragma unroll
    for (int nt = 0; nt < 2; nt++)
#pragma unroll
        for (int e = 0; e < 4; e++) sc[nt][e] = 0.0f;

#pragma unroll
    for (int kc = 0; kc < 4; kc++) {
        uint32_t qa[4], kb[4];
        ldsm_x4(qa, qPtr + kc * 32);
        ldsm_x4(kb, kPtr + kc * 32);
        mma_f16(sc[0], qa, kb[0], kb[2]);
        mma_f16(sc[1], qa, kb[1], kb[3]);
    }

#pragma unroll
    for (int nt = 0; nt < 2; nt++)
#pragma unroll
        for (int e = 0; e < 4; e++) {
            int row = (e < 2) ? gp : gp + 8;
            int col = nt * 8 + tg * 2 + (e & 1);
            sc[nt][e] = sc[nt][e] * 0.125f + stab[sbkt[col - row + 15] * NHEAD + h];
        }

    float m0 = fmaxf(fmaxf(sc[0][0], sc[0][1]), fmaxf(sc[1][0], sc[1][1]));
    float m1 = fmaxf(fmaxf(sc[0][2], sc[0][3]), fmaxf(sc[1][2], sc[1][3]));
    m0 = fmaxf(m0, __shfl_xor_sync(0xffffffffu, m0, 1));
    m0 = fmaxf(m0, __shfl_xor_sync(0xffffffffu, m0, 2));
    m1 = fmaxf(m1, __shfl_xor_sync(0xffffffffu, m1, 1));
    m1 = fmaxf(m1, __shfl_xor_sync(0xffffffffu, m1, 2));
#pragma unroll
    for (int nt = 0; nt < 2; nt++) {
        sc[nt][0] = __expf(sc[nt][0] - m0);
        sc[nt][1] = __expf(sc[nt][1] - m0);
        sc[nt][2] = __expf(sc[nt][2] - m1);
        sc[nt][3] = __expf(sc[nt][3] - m1);
    }
    float s0 = sc[0][0] + sc[0][1] + sc[1][0] + sc[1][1];
    float s1 = sc[0][2] + sc[0][3] + sc[1][2] + sc[1][3];
    s0 += __shfl_xor_sync(0xffffffffu, s0, 1);
    s0 += __shfl_xor_sync(0xffffffffu, s0, 2);
    s1 += __shfl_xor_sync(0xffffffffu, s1, 1);
    s1 += __shfl_xor_sync(0xffffffffu, s1, 2);
    float i0 = 1.0f / s0, i1 = 1.0f / s1;
#pragma unroll
    for (int nt = 0; nt < 2; nt++) {
        sc[nt][0] *= i0; sc[nt][1] *= i0;
        sc[nt][2] *= i1; sc[nt][3] *= i1;
    }

    uint32_t pa[4];
    {
        __half2 t0 = __floats2half2_rn(sc[0][0], sc[0][1]);
        __half2 t1 = __floats2half2_rn(sc[0][2], sc[0][3]);
        __half2 t2 = __floats2half2_rn(sc[1][0], sc[1][1]);
        __half2 t3 = __floats2half2_rn(sc[1][2], sc[1][3]);
        pa[0] = *(uint32_t*)&t0; pa[1] = *(uint32_t*)&t1;
        pa[2] = *(uint32_t*)&t2; pa[3] = *(uint32_t*)&t3;
    }

    float oc[8][4];
#pragma unroll
    for (int nt = 0; nt < 8; nt++)
#pragma unroll
        for (int e = 0; e < 4; e++) oc[nt][e] = 0.0f;
#pragma unroll
    for (int c2 = 0; c2 < 4; c2++) {
        uint32_t vb[4];
        ldsm_x4_t(vb, vPtr + c2 * 32);
        mma_f16(oc[c2 * 2 + 0], pa, vb[0], vb[1]);
        mma_f16(oc[c2 * 2 + 1], pa, vb[2], vb[3]);
    }

    __syncwarp();
#pragma unroll
    for (int nt = 0; nt < 8; nt++) {
        __half2 h0 = __floats2half2_rn(oc[nt][0], oc[nt][1]);
        __half2 h1 = __floats2half2_rn(oc[nt][2], oc[nt][3]);
        *(__half2*)&sQ[warp][gp][nt * 8 + tg * 2]     = h0;
        *(__half2*)&sQ[warp][gp + 8][nt * 8 + tg * 2] = h1;
    }
    __syncwarp();
    for (int t = lane; t < 128; t += 32) {
        int f = t >> 3, c = (t & 7) * 8;
        *(uint4*)&g_h16[base + (size_t)f * CDIM + c] = *(const uint4*)&sQ[warp][f][c];
    }
}

// ---------------------------------------------------------------------------
extern "C" void kernel_launch(void* const* d_in, const int* in_sizes, int n_in,
                              void* d_out, int out_size)
{
    const float* X   = (const float*)d_in[0];
    const float* Wq  = (const float*)d_in[1];
    const float* Wk  = (const float*)d_in[2];
    const float* Wv  = (const float*)d_in[3];
    const float* Wo  = (const float*)d_in[4];
    const float* bo  = (const float*)d_in[5];
    const float* tab = (const float*)d_in[6];
    (void)in_sizes; (void)n_in; (void)out_size;

    cvt_x_kernel<<<65536, 256>>>(X);
    prep_w_kernel<<<dim3(16, 16, 4), dim3(32, 8)>>>(Wq, Wk, Wv, Wo);

    dim3 gq(12, 1024);
    qkv_kernel<<<gq, 256>>>();

    attn_kernel<<<16384, 128>>>(tab);

    dim3 go(4, 1024);
    out_kernel<<<go, 256>>>(bo, (float*)d_out);
}

// round 15
// speedup vs baseline: 1.5916x; 1.5916x over previous
#include <cuda_runtime.h>
#include <cuda_fp16.h>
#include <cstdint>

// ---------------------------------------------------------------------------
// TemporalAttention on sm_103a (compute_103-safe: mma.sync + ldmatrix + cp.async).
// GEMMs: fp16 x fp16 -> fp32 mma.sync.m16n8k16, CTA tile 128x128, warp 64x32,
//        cp.async double-buffered 64-wide K stages with XOR (SW128) swizzle.
// Attention: per-warp tensor-core flash (S-mma -> reg softmax -> PV-mma).
// B=8192, F=16, C=512, H=8, Dh=64.  M = B*F = 131072.
// ---------------------------------------------------------------------------

#define CDIM  512
#define NHEAD 8
#define DHEAD 64
#define NFRM  16

__device__ __half g_qh[67108864];
__device__ __half g_kh[67108864];
__device__ __half g_vh[67108864];
__device__ __half g_h16[67108864];    // cvt(X) each launch; attn overwrites with its output
__device__ __half g_w16[4][262144];   // transposed fp16 weights: w[n][k] = W[k][n]

// ------------------------------ helpers ------------------------------------
__device__ __forceinline__ uint32_t smem_u32(const void* p) {
    uint32_t a;
    asm("{ .reg .u64 t; cvta.to.shared.u64 t, %1; cvt.u32.u64 %0, t; }" : "=r"(a) : "l"(p));
    return a;
}

__device__ __forceinline__ void ldsm_x4(uint32_t r[4], uint32_t addr) {
    asm volatile("ldmatrix.sync.aligned.m8n8.x4.shared.b16 {%0,%1,%2,%3}, [%4];"
                 : "=r"(r[0]), "=r"(r[1]), "=r"(r[2]), "=r"(r[3]) : "r"(addr));
}
__device__ __forceinline__ void ldsm_x4_t(uint32_t r[4], uint32_t addr) {
    asm volatile("ldmatrix.sync.aligned.m8n8.x4.trans.shared.b16 {%0,%1,%2,%3}, [%4];"
                 : "=r"(r[0]), "=r"(r[1]), "=r"(r[2]), "=r"(r[3]) : "r"(addr));
}

__device__ __forceinline__ void mma_f16(float c[4], const uint32_t a[4],
                                        uint32_t b0, uint32_t b1) {
    asm volatile(
        "mma.sync.aligned.m16n8k16.row.col.f32.f16.f16.f32 "
        "{%0,%1,%2,%3},{%4,%5,%6,%7},{%8,%9},{%0,%1,%2,%3};"
        : "+f"(c[0]), "+f"(c[1]), "+f"(c[2]), "+f"(c[3])
        : "r"(a[0]), "r"(a[1]), "r"(a[2]), "r"(a[3]), "r"(b0), "r"(b1));
}

__device__ __forceinline__ void cp16(uint32_t dst, const void* src) {
    asm volatile("cp.async.cg.shared.global [%0], [%1], 16;" :: "r"(dst), "l"(src));
}

// ---------------------------------------------------------------------------
// 128x128x512 tile GEMM: C = A16[rowBase:+128,:] @ Bw16[colBase:+128,:]^T
// A16 [M,512] fp16 row-major; Bw16 [512,512] fp16 stored [n][k] row-major.
// 256 threads = 8 warps (2m x 4n), warp tile 64x32.
// K staged 64-wide: rows are exactly 128B, XOR-swizzled (chunk ^= row&7),
// cp.async double-buffered (8 stages), 2 CTAs/SM.
// Output: fp16 (Ch) when Ch != nullptr, else fp32 (+bias) to Cf.
// ---------------------------------------------------------------------------
__device__ __forceinline__ void stage_in(uint32_t aB, uint32_t bB,
                                         const __half* Ag, const __half* Bg, int kt,
                                         int tid)
{
#pragma unroll
    for (int i = 0; i < 4; i++) {
        int cc  = tid + i * 256;        // 0..1023 chunk id
        int row = cc >> 3;
        int ch  = cc & 7;
        uint32_t dst = (uint32_t)(row * 128 + ((ch ^ (row & 7)) << 4));
        cp16(aB + dst, Ag + (size_t)row * CDIM + kt + ch * 8);
        cp16(bB + dst, Bg + (size_t)row * CDIM + kt + ch * 8);
    }
    asm volatile("cp.async.commit_group;" ::: "memory");
}

__device__ __forceinline__ void gemm_tc(const __half* __restrict__ A16,
                                        const __half* __restrict__ Bw16,
                                        float* __restrict__ Cf, __half* __restrict__ Ch,
                                        const float* __restrict__ bias,
                                        int rowBase, int colBase)
{
    __shared__ alignas(128) __half sA[2][128 * 64];
    __shared__ alignas(128) __half sB[2][128 * 64];

    const int tid  = threadIdx.x;
    const int lane = tid & 31;
    const int warp = tid >> 5;
    const int m0 = (warp >> 2) * 64;
    const int n0 = (warp & 3) * 32;
    const int tg = lane & 3;
    const int gp = lane >> 2;

    float acc[4][4][4];
#pragma unroll
    for (int mt = 0; mt < 4; mt++)
#pragma unroll
        for (int nt = 0; nt < 4; nt++)
#pragma unroll
            for (int r = 0; r < 4; r++) acc[mt][nt][r] = 0.0f;

    const uint32_t aAddr[2] = { smem_u32(sA[0]), smem_u32(sA[1]) };
    const uint32_t bAddr[2] = { smem_u32(sB[0]), smem_u32(sB[1]) };

    // ldmatrix per-lane geometry (swizzle XOR value is row&7, constant per lane)
    const int aRow = lane & 15;            // row within 16-row matrix pair
    const int aX   = aRow & 7;
    const int aHi  = (lane >> 4) & 1;      // 16B half of the 32B k16 chunk
    const int bRow = (lane & 7) + ((lane >> 4) & 1) * 8;
    const int bX   = lane & 7;
    const int bLo  = (lane >> 3) & 1;

    const __half* Ag = A16 + (size_t)rowBase * CDIM;
    const __half* Bg = Bw16 + (size_t)colBase * CDIM;

    stage_in(aAddr[0], bAddr[0], Ag, Bg, 0, tid);

    for (int s = 0; s < 8; s++) {
        const int buf = s & 1;
        if (s < 7) {
            stage_in(aAddr[buf ^ 1], bAddr[buf ^ 1], Ag, Bg, (s + 1) * 64, tid);
            asm volatile("cp.async.wait_group 1;" ::: "memory");
        } else {
            asm volatile("cp.async.wait_group 0;" ::: "memory");
        }
        __syncthreads();

        const uint32_t aP = aAddr[buf];
        const uint32_t bP = bAddr[buf];
#pragma unroll
        for (int k16 = 0; k16 < 4; k16++) {
            uint32_t af[4][4];
            uint32_t bf[2][4];
            const int cA = (k16 * 2 + aHi) ^ aX;
            const int cB0 = (k16 * 2 + bLo) ^ bX;
#pragma unroll
            for (int mt = 0; mt < 4; mt++)
                ldsm_x4(af[mt], aP + (uint32_t)((m0 + mt * 16 + aRow) * 128 + (cA << 4)));
#pragma unroll
            for (int nt2 = 0; nt2 < 2; nt2++)
                ldsm_x4(bf[nt2], bP + (uint32_t)((n0 + nt2 * 16 + bRow) * 128 + (cB0 << 4)));
#pragma unroll
            for (int mt = 0; mt < 4; mt++)
#pragma unroll
                for (int nt = 0; nt < 4; nt++)
                    mma_f16(acc[mt][nt], af[mt],
                            bf[nt >> 1][(nt & 1) * 2], bf[nt >> 1][(nt & 1) * 2 + 1]);
        }
        __syncthreads();
    }

#pragma unroll
    for (int mt = 0; mt < 4; mt++) {
#pragma unroll
        for (int nt = 0; nt < 4; nt++) {
            int r   = rowBase + m0 + mt * 16 + gp;
            int cix = colBase + n0 + nt * 8 + tg * 2;
            if (Ch) {
                __half2 h0 = __floats2half2_rn(acc[mt][nt][0], acc[mt][nt][1]);
                __half2 h1 = __floats2half2_rn(acc[mt][nt][2], acc[mt][nt][3]);
                *(__half2*)&Ch[(size_t)r * CDIM + cix]       = h0;
                *(__half2*)&Ch[(size_t)(r + 8) * CDIM + cix] = h1;
            } else {
                float2 t0 = make_float2(acc[mt][nt][0], acc[mt][nt][1]);
                float2 t1 = make_float2(acc[mt][nt][2], acc[mt][nt][3]);
                float b0v = bias[cix], b1v = bias[cix + 1];
                t0.x += b0v; t0.y += b1v;
                t1.x += b0v; t1.y += b1v;
                *(float2*)&Cf[(size_t)r * CDIM + cix]       = t0;
                *(float2*)&Cf[(size_t)(r + 8) * CDIM + cix] = t1;
            }
        }
    }
}

// grid (12, 1024): x>>2 selects q/k/v, x&3 selects 128-col slab
__global__ void __launch_bounds__(256, 2)
qkv_kernel()
{
    int sel = blockIdx.x >> 2;
    __half* Cd = (sel == 0) ? g_qh : (sel == 1) ? g_kh : g_vh;
    gemm_tc(g_h16, g_w16[sel], nullptr, Cd, nullptr, blockIdx.y * 128, (blockIdx.x & 3) * 128);
}

// grid (4, 1024)
__global__ void __launch_bounds__(256, 2)
out_kernel(const float* __restrict__ bo, float* __restrict__ out)
{
    gemm_tc(g_h16, g_w16[3], out, nullptr, bo, blockIdx.y * 128, blockIdx.x * 128);
}

// ---------------------------------------------------------------------------
// prep: X fp32 -> fp16 ; W[k][n] fp32 -> w16[n][k] fp16 (transposed)
// ---------------------------------------------------------------------------
__global__ void cvt_x_kernel(const float* __restrict__ X)
{
    size_t i = ((size_t)blockIdx.x * blockDim.x + threadIdx.x) * 4;
    float4 v = *(const float4*)(X + i);
    __half2 hh[2];
    hh[0] = __floats2half2_rn(v.x, v.y);
    hh[1] = __floats2half2_rn(v.z, v.w);
    *(uint2*)&g_h16[i] = *(uint2*)hh;
}

__global__ void prep_w_kernel(const float* __restrict__ Wq, const float* __restrict__ Wk,
                              const float* __restrict__ Wv, const float* __restrict__ Wo)
{
    __shared__ float t[32][33];
    const float* W = (blockIdx.z == 0) ? Wq : (blockIdx.z == 1) ? Wk
                   : (blockIdx.z == 2) ? Wv : Wo;
    int n0 = blockIdx.x * 32, k0 = blockIdx.y * 32;
    for (int rr = threadIdx.y; rr < 32; rr += 8)
        t[rr][threadIdx.x] = W[(size_t)(k0 + rr) * CDIM + n0 + threadIdx.x];
    __syncthreads();
    for (int rr = threadIdx.y; rr < 32; rr += 8)
        g_w16[blockIdx.z][(size_t)(n0 + rr) * CDIM + k0 + threadIdx.x] =
            __float2half_rn(t[threadIdx.x][rr]);
}

// ---------------------------------------------------------------------------
// Attention: one warp per (batch, head). Tensor-core S = Q K^T (m16n8k16),
// softmax in registers (S-acc layout == next mma's A-frag layout), then
// O = P V with V fragments via ldmatrix.trans. Output fp16 into g_h16.
// ---------------------------------------------------------------------------
__device__ __forceinline__ int t5_bucket(int rel) {  // rel = j - i
    int n = -rel;
    int ret = 0;
    if (n < 0) { ret = 16; n = -n; }
    if (n < 8) return ret + n;
    int v = 8 + (int)(logf((float)n * 0.125f) * (8.0f / logf(16.0f)));
    if (v > 15) v = 15;
    return ret + v;
}

__global__ void __launch_bounds__(128)
attn_kernel(const float* __restrict__ table)
{
    __shared__ alignas(16) __half sQ[4][NFRM][72];   // reused as output staging
    __shared__ alignas(16) __half sK[4][NFRM][72];
    __shared__ alignas(16) __half sV[4][NFRM][72];
    __shared__ float stab[32 * NHEAD];
    __shared__ int   sbkt[31];

    const int tid  = threadIdx.x;
    const int lane = tid & 31;
    const int warp = tid >> 5;

    for (int t = tid; t < 32 * NHEAD; t += 128) stab[t] = table[t];
    if (tid < 31) sbkt[tid] = t5_bucket(tid - 15);
    __syncthreads();

    const int b = blockIdx.x >> 1;
    const int h = ((blockIdx.x & 1) << 2) + warp;
    const size_t base = (size_t)b * NFRM * CDIM + (size_t)h * DHEAD;

    for (int t = lane; t < 128; t += 32) {
        int f = t >> 3, c = (t & 7) * 8;
        size_t g = base + (size_t)f * CDIM + c;
        *(uint4*)&sQ[warp][f][c] = *(const uint4*)&g_qh[g];
        *(uint4*)&sK[warp][f][c] = *(const uint4*)&g_kh[g];
        *(uint4*)&sV[warp][f][c] = *(const uint4*)&g_vh[g];
    }
    __syncwarp();

    const uint32_t lrow = (uint32_t)((lane & 15) * 144 + ((lane >> 4) & 1) * 16);
    const uint32_t qPtr = smem_u32(&sQ[warp][0][0]) + lrow;
    const uint32_t kPtr = smem_u32(&sK[warp][0][0]) + lrow;
    const uint32_t vPtr = smem_u32(&sV[warp][0][0]) + lrow;

    const int gp = lane >> 2;
    const int tg = lane & 3;

    float sc[2][4];
#pragma unroll
    for (int nt = 0; nt < 2; nt++)
#pragma unroll
        for (int e = 0; e < 4; e++) sc[nt][e] = 0.0f;

#pragma unroll
    for (int kc = 0; kc < 4; kc++) {
        uint32_t qa[4], kb[4];
        ldsm_x4(qa, qPtr + kc * 32);
        ldsm_x4(kb, kPtr + kc * 32);
        mma_f16(sc[0], qa, kb[0], kb[2]);
        mma_f16(sc[1], qa, kb[1], kb[3]);
    }

#pragma unroll
    for (int nt = 0; nt < 2; nt++)
#pragma unroll
        for (int e = 0; e < 4; e++) {
            int row = (e < 2) ? gp : gp + 8;
            int col = nt * 8 + tg * 2 + (e & 1);
            sc[nt][e] = sc[nt][e] * 0.125f + stab[sbkt[col - row + 15] * NHEAD + h];
        }

    float m0 = fmaxf(fmaxf(sc[0][0], sc[0][1]), fmaxf(sc[1][0], sc[1][1]));
    float m1 = fmaxf(fmaxf(sc[0][2], sc[0][3]), fmaxf(sc[1][2], sc[1][3]));
    m0 = fmaxf(m0, __shfl_xor_sync(0xffffffffu, m0, 1));
    m0 = fmaxf(m0, __shfl_xor_sync(0xffffffffu, m0, 2));
    m1 = fmaxf(m1, __shfl_xor_sync(0xffffffffu, m1, 1));
    m1 = fmaxf(m1, __shfl_xor_sync(0xffffffffu, m1, 2));
#pragma unroll
    for (int nt = 0; nt < 2; nt++) {
        sc[nt][0] = __expf(sc[nt][0] - m0);
        sc[nt][1] = __expf(sc[nt][1] - m0);
        sc[nt][2] = __expf(sc[nt][2] - m1);
        sc[nt][3] = __expf(sc[nt][3] - m1);
    }
    float s0 = sc[0][0] + sc[0][1] + sc[1][0] + sc[1][1];
    float s1 = sc[0][2] + sc[0][3] + sc[1][2] + sc[1][3];
    s0 += __shfl_xor_sync(0xffffffffu, s0, 1);
    s0 += __shfl_xor_sync(0xffffffffu, s0, 2);
    s1 += __shfl_xor_sync(0xffffffffu, s1, 1);
    s1 += __shfl_xor_sync(0xffffffffu, s1, 2);
    float i0 = 1.0f / s0, i1 = 1.0f / s1;
#pragma unroll
    for (int nt = 0; nt < 2; nt++) {
        sc[nt][0] *= i0; sc[nt][1] *= i0;
        sc[nt][2] *= i1; sc[nt][3] *= i1;
    }

    uint32_t pa[4];
    {
        __half2 t0 = __floats2half2_rn(sc[0][0], sc[0][1]);
        __half2 t1 = __floats2half2_rn(sc[0][2], sc[0][3]);
        __half2 t2 = __floats2half2_rn(sc[1][0], sc[1][1]);
        __half2 t3 = __floats2half2_rn(sc[1][2], sc[1][3]);
        pa[0] = *(uint32_t*)&t0; pa[1] = *(uint32_t*)&t1;
        pa[2] = *(uint32_t*)&t2; pa[3] = *(uint32_t*)&t3;
    }

    float oc[8][4];
#pragma unroll
    for (int nt = 0; nt < 8; nt++)
#pragma unroll
        for (int e = 0; e < 4; e++) oc[nt][e] = 0.0f;
#pragma unroll
    for (int c2 = 0; c2 < 4; c2++) {
        uint32_t vb[4];
        ldsm_x4_t(vb, vPtr + c2 * 32);
        mma_f16(oc[c2 * 2 + 0], pa, vb[0], vb[1]);
        mma_f16(oc[c2 * 2 + 1], pa, vb[2], vb[3]);
    }

    __syncwarp();
#pragma unroll
    for (int nt = 0; nt < 8; nt++) {
        __half2 h0 = __floats2half2_rn(oc[nt][0], oc[nt][1]);
        __half2 h1 = __floats2half2_rn(oc[nt][2], oc[nt][3]);
        *(__half2*)&sQ[warp][gp][nt * 8 + tg * 2]     = h0;
        *(__half2*)&sQ[warp][gp + 8][nt * 8 + tg * 2] = h1;
    }
    __syncwarp();
    for (int t = lane; t < 128; t += 32) {
        int f = t >> 3, c = (t & 7) * 8;
        *(uint4*)&g_h16[base + (size_t)f * CDIM + c] = *(const uint4*)&sQ[warp][f][c];
    }
}

// ---------------------------------------------------------------------------
extern "C" void kernel_launch(void* const* d_in, const int* in_sizes, int n_in,
                              void* d_out, int out_size)
{
    const float* X   = (const float*)d_in[0];
    const float* Wq  = (const float*)d_in[1];
    const float* Wk  = (const float*)d_in[2];
    const float* Wv  = (const float*)d_in[3];
    const float* Wo  = (const float*)d_in[4];
    const float* bo  = (const float*)d_in[5];
    const float* tab = (const float*)d_in[6];
    (void)in_sizes; (void)n_in; (void)out_size;

    cvt_x_kernel<<<65536, 256>>>(X);
    prep_w_kernel<<<dim3(16, 16, 4), dim3(32, 8)>>>(Wq, Wk, Wv, Wo);

    dim3 gq(12, 1024);
    qkv_kernel<<<gq, 256>>>();

    attn_kernel<<<16384, 128>>>(tab);

    dim3 go(4, 1024);
    out_kernel<<<go, 256>>>(bo, (float*)d_out);
}